// round 13
// baseline (speedup 1.0000x reference)
#include <cuda_runtime.h>
#include <math.h>
#include <cstdint>

#define EMBED   768
#define NHEADS  12
#define HDIM    64
#define BATCH   16
#define SEQ     1024
#define MTOT    (BATCH*SEQ)      // 16384
#define BHEADS  (BATCH*NHEADS)   // 192
#define ATT_SCALE 0.125f

// Scratch (allocation-free rule: __device__ globals)
__device__ __align__(16) float g_Q[BHEADS*SEQ*HDIM];   // tf32-valued fp32
__device__ __align__(16) float g_K[BHEADS*SEQ*HDIM];
__device__ __align__(16) float g_V[BHEADS*SEQ*HDIM];
__device__ __align__(16) float g_A[BHEADS*SEQ*HDIM];   // tf32-valued fp32

// Pre-converted tf32 operands (bits stored as unsigned)
__device__ __align__(16) unsigned g_xt [MTOT*EMBED];
__device__ __align__(16) unsigned g_Wqt[EMBED*EMBED];
__device__ __align__(16) unsigned g_Wkt[EMBED*EMBED];
__device__ __align__(16) unsigned g_Wvt[EMBED*EMBED];
__device__ __align__(16) unsigned g_Wot[EMBED*EMBED];

// ---------------------------------------------------------------------------
// helpers
// ---------------------------------------------------------------------------
__device__ __forceinline__ unsigned f2tf(float f) {
    unsigned u;
    asm("cvt.rna.tf32.f32 %0, %1;" : "=r"(u) : "f"(f));
    return u;
}
__device__ __forceinline__ float tf32r(float f) { return __uint_as_float(f2tf(f)); }

// D += A*B   (m16n8k8 tf32, row.col)
__device__ __forceinline__ void mma8(float* d, const unsigned* a, const unsigned* b) {
    asm volatile(
        "mma.sync.aligned.m16n8k8.row.col.f32.tf32.tf32.f32 "
        "{%0,%1,%2,%3}, {%4,%5,%6,%7}, {%8,%9}, {%0,%1,%2,%3};"
        : "+f"(d[0]), "+f"(d[1]), "+f"(d[2]), "+f"(d[3])
        : "r"(a[0]), "r"(a[1]), "r"(a[2]), "r"(a[3]), "r"(b[0]), "r"(b[1]));
}

__device__ __forceinline__ void cpa16(unsigned saddr, const void* g) {
    asm volatile("cp.async.cg.shared.global [%0], [%1], 16;" :: "r"(saddr), "l"(g));
}
__device__ __forceinline__ void cpa_commit() {
    asm volatile("cp.async.commit_group;" ::: "memory");
}

// ---------------------------------------------------------------------------
// Pre-conversion: fp32 -> tf32 bits (all 5 operands, one launch)
// ---------------------------------------------------------------------------
__global__ void conv_all(const float* __restrict__ x,  const float* __restrict__ wq,
                         const float* __restrict__ wk, const float* __restrict__ wv,
                         const float* __restrict__ wo) {
    const int z = blockIdx.y;
    const float* src = (z==0) ? x : (z==1) ? wq : (z==2) ? wk : (z==3) ? wv : wo;
    unsigned*    dst = (z==0) ? g_xt : (z==1) ? g_Wqt : (z==2) ? g_Wkt : (z==3) ? g_Wvt : g_Wot;
    const int n4 = (z==0) ? MTOT*EMBED/4 : EMBED*EMBED/4;
    int i = blockIdx.x*blockDim.x + threadIdx.x;
    if (i < n4) {
        float4 v = ((const float4*)src)[i];
        ((uint4*)dst)[i] = make_uint4(f2tf(v.x), f2tf(v.y), f2tf(v.z), f2tf(v.w));
    }
}

// ---------------------------------------------------------------------------
// TF32 GEMM, cp.async double-buffered, 512 threads (16 warps = 4/SMSP).
// CTA tile 256(M) x 128(N), ktile 32. Warp tile 64x32.
// smem row-major [row][KP=36] per operand (conflict-free fragment LDS).
// ---------------------------------------------------------------------------
#define KP    36
#define ASTW  (256*KP)          // 9216 words
#define BSTW  (128*KP)          // 4608 words
#define STGW  (ASTW+BSTW)       // 13824 words per stage

// A fill: 256 rows x 8 chunks = 2048 chunks over 512 threads -> 4 iters
__device__ __forceinline__ void issue_A(unsigned* Sm, const unsigned* __restrict__ src,
                                        int row0, int k0, int tid) {
    #pragma unroll
    for (int it = 0; it < 4; it++) {
        int lin = tid + 512*it;
        int rr = lin >> 3, ch = lin & 7;
        unsigned sa = (unsigned)__cvta_generic_to_shared(&Sm[rr*KP + ch*4]);
        cpa16(sa, &src[(size_t)(row0+rr)*EMBED + k0 + ch*4]);
    }
}
// B fill: 128 rows x 8 chunks = 1024 chunks -> 2 iters
__device__ __forceinline__ void issue_B(unsigned* Sm, const unsigned* __restrict__ src,
                                        int row0, int k0, int tid) {
    #pragma unroll
    for (int it = 0; it < 2; it++) {
        int lin = tid + 512*it;
        int rr = lin >> 3, ch = lin & 7;
        unsigned sa = (unsigned)__cvta_generic_to_shared(&Sm[rr*KP + ch*4]);
        cpa16(sa, &src[(size_t)(row0+rr)*EMBED + k0 + ch*4]);
    }
}
// A fill gathering from g_A [b][h][n][d]
__device__ __forceinline__ void issue_A_gather(unsigned* Sm, int m0, int k0, int tid) {
    #pragma unroll
    for (int it = 0; it < 4; it++) {
        int lin = tid + 512*it;
        int rr = lin >> 3, ch = lin & 7;
        const int m  = m0 + rr;
        const int b_ = m >> 10;
        const int nn = m & 1023;
        const int k  = k0 + ch*4;
        const int h  = k >> 6;
        const int d  = k & 63;
        unsigned sa = (unsigned)__cvta_generic_to_shared(&Sm[rr*KP + ch*4]);
        cpa16(sa, &g_A[(((size_t)b_*NHEADS + h)*SEQ + nn)*HDIM + d]);
    }
}

// warp tile 64x32: a[4][4] (rows wm+16i), b[4][2] (cols wn+8j), 16 mmas/ktile
__device__ __forceinline__ void compute_stage(const unsigned* __restrict__ As,
                                              const unsigned* __restrict__ Bs,
                                              float acc[4][4][4],
                                              int wm, int wn, int g, int s) {
    #pragma unroll
    for (int kt = 0; kt < 4; kt++) {
        const int kc = kt*8 + s;
        unsigned a[4][4], b[4][2];
        #pragma unroll
        for (int i = 0; i < 4; i++) {
            const unsigned* p = &As[(wm + 16*i + g)*KP + kc];
            a[i][0] = p[0];
            a[i][1] = p[8*KP];
            a[i][2] = p[4];
            a[i][3] = p[8*KP + 4];
        }
        #pragma unroll
        for (int j = 0; j < 4; j++) {
            const unsigned* p = &Bs[(wn + 8*j + g)*KP + kc];
            b[j][0] = p[0];
            b[j][1] = p[4];
        }
        #pragma unroll
        for (int i = 0; i < 4; i++)
            #pragma unroll
            for (int j = 0; j < 4; j++)
                mma8(acc[i][j], a[i], b[j]);
    }
}

__global__ __launch_bounds__(512) void qkv_gemm_tc(
    const float* __restrict__ bq, const float* __restrict__ bk, const float* __restrict__ bv)
{
    const int p = blockIdx.z;
    const unsigned* __restrict__ Wt   = (p==0) ? g_Wqt : (p==1 ? g_Wkt : g_Wvt);
    const float*    __restrict__ bias = (p==0) ? bq : (p==1 ? bk : bv);
    float*          __restrict__ outp = (p==0) ? g_Q : (p==1 ? g_K : g_V);

    extern __shared__ unsigned smg[];

    const int tid  = threadIdx.x;
    const int w    = tid >> 5;
    const int lane = tid & 31;
    const int g    = lane >> 2;
    const int s    = lane & 3;
    const int wm   = (w & 3) * 64;      // 4 warps along M
    const int wn   = (w >> 2) * 32;     // 4 warps along N
    const int m0   = blockIdx.y * 256;
    const int n0   = blockIdx.x * 128;

    float acc[4][4][4];
    #pragma unroll
    for (int i = 0; i < 4; i++)
        #pragma unroll
        for (int j = 0; j < 4; j++)
            #pragma unroll
            for (int c = 0; c < 4; c++) acc[i][j][c] = 0.f;

    // prologue: stage 0
    issue_A(smg,        g_xt, m0, 0, tid);
    issue_B(smg + ASTW, Wt,   n0, 0, tid);
    cpa_commit();

    int buf = 0;
    for (int k0 = 0; k0 < EMBED; k0 += 32) {
        const bool more = (k0 + 32) < EMBED;
        if (more) {
            unsigned* st = smg + (buf^1)*STGW;
            issue_A(st,        g_xt, m0, k0+32, tid);
            issue_B(st + ASTW, Wt,   n0, k0+32, tid);
            cpa_commit();
            asm volatile("cp.async.wait_group 1;" ::: "memory");
        } else {
            asm volatile("cp.async.wait_group 0;" ::: "memory");
        }
        __syncthreads();
        const unsigned* st = smg + buf*STGW;
        compute_stage(st, st + ASTW, acc, wm, wn, g, s);
        __syncthreads();
        buf ^= 1;
    }

    // Epilogue: scatter to [b][h][n][d], tf32-rounded + bias
    #pragma unroll
    for (int i = 0; i < 4; i++) {
        const int m  = m0 + wm + 16*i + g;
        const int b_ = m >> 10;
        const int nn = m & 1023;
        #pragma unroll
        for (int j = 0; j < 4; j++) {
            const int c  = n0 + wn + 8*j + 2*s;
            const int h  = c >> 6;
            const int d  = c & 63;
            const float b0v = bias[c], b1v = bias[c+1];
            float2 v0 = make_float2(tf32r(acc[i][j][0] + b0v), tf32r(acc[i][j][1] + b1v));
            float2 v1 = make_float2(tf32r(acc[i][j][2] + b0v), tf32r(acc[i][j][3] + b1v));
            *(float2*)&outp[(((size_t)b_*NHEADS + h)*SEQ + nn    )*HDIM + d] = v0;
            *(float2*)&outp[(((size_t)b_*NHEADS + h)*SEQ + nn + 8)*HDIM + d] = v1;
        }
    }
}

__global__ __launch_bounds__(512) void out_gemm_tc(
    const float* __restrict__ bo, float* __restrict__ out)
{
    extern __shared__ unsigned smg[];

    const int tid  = threadIdx.x;
    const int w    = tid >> 5;
    const int lane = tid & 31;
    const int g    = lane >> 2;
    const int s    = lane & 3;
    const int wm   = (w & 3) * 64;
    const int wn   = (w >> 2) * 32;
    const int m0   = blockIdx.y * 256;
    const int n0   = blockIdx.x * 128;

    float acc[4][4][4];
    #pragma unroll
    for (int i = 0; i < 4; i++)
        #pragma unroll
        for (int j = 0; j < 4; j++)
            #pragma unroll
            for (int c = 0; c < 4; c++) acc[i][j][c] = 0.f;

    issue_A_gather(smg, m0, 0, tid);
    issue_B(smg + ASTW, g_Wot, n0, 0, tid);
    cpa_commit();

    int buf = 0;
    for (int k0 = 0; k0 < EMBED; k0 += 32) {
        const bool more = (k0 + 32) < EMBED;
        if (more) {
            unsigned* st = smg + (buf^1)*STGW;
            issue_A_gather(st, m0, k0+32, tid);
            issue_B(st + ASTW, g_Wot, n0, k0+32, tid);
            cpa_commit();
            asm volatile("cp.async.wait_group 1;" ::: "memory");
        } else {
            asm volatile("cp.async.wait_group 0;" ::: "memory");
        }
        __syncthreads();
        const unsigned* st = smg + buf*STGW;
        compute_stage(st, st + ASTW, acc, wm, wn, g, s);
        __syncthreads();
        buf ^= 1;
    }

    // Epilogue: row-major fp32 out + bias (full precision)
    #pragma unroll
    for (int i = 0; i < 4; i++) {
        const int m = m0 + wm + 16*i + g;
        #pragma unroll
        for (int j = 0; j < 4; j++) {
            const int c = n0 + wn + 8*j + 2*s;
            const float b0v = bo[c], b1v = bo[c+1];
            float2 v0 = make_float2(acc[i][j][0] + b0v, acc[i][j][1] + b1v);
            float2 v1 = make_float2(acc[i][j][2] + b0v, acc[i][j][3] + b1v);
            *(float2*)&out[(size_t)m*EMBED + c]     = v0;
            *(float2*)&out[(size_t)(m+8)*EMBED + c] = v1;
        }
    }
}

// ---------------------------------------------------------------------------
// Flash attention (unchanged, proven): mma.sync tf32, double-buffered K/V.
// Br=128 q-rows/CTA, Bc=64 keys/tile, 256 threads / 8 warps.
// ---------------------------------------------------------------------------
#define KSTR  136
#define PSTR  72
#define KVW   (64*PSTR)

__global__ __launch_bounds__(256) void attn_tc()
{
    extern __shared__ unsigned smu[];
    unsigned* sQ = smu;                    // [d=64][m+pad=136]
    unsigned* sP = smu;                    // [m=128][key+pad=72]
    unsigned* sK = smu + 9216;             // 2 buffers [d][key+pad]
    unsigned* sV = sK + 2*KVW;             // 2 buffers [key][d+pad]

    const int tid  = threadIdx.x;
    const int w    = tid >> 5;
    const int lane = tid & 31;
    const int g    = lane >> 2;
    const int s    = lane & 3;
    const int bh   = blockIdx.y;
    const int q0   = blockIdx.x * 128;
    const int r0   = 16*w + g;
    const int r1   = r0 + 8;

    const float* __restrict__ Qg = g_Q + ((size_t)bh*SEQ + q0)*HDIM;
    const float* __restrict__ Kg = g_K + (size_t)bh*SEQ*HDIM;
    const float* __restrict__ Vg = g_V + (size_t)bh*SEQ*HDIM;
    float* __restrict__ Og = g_A + ((size_t)bh*SEQ + q0)*HDIM;

    float4 kreg[4], vreg[4];

    #pragma unroll
    for (int it = 0; it < 4; it++) {
        int lin = tid + 256*it;
        int rr = lin >> 4, dq = lin & 15;
        kreg[it] = *(const float4*)&Kg[(size_t)rr*HDIM + dq*4];
        vreg[it] = *(const float4*)&Vg[(size_t)rr*HDIM + dq*4];
    }

    #pragma unroll
    for (int it = 0; it < 8; it++) {
        int lin = tid + 256*it;
        int rr = lin >> 4;
        int dq = lin & 15;
        const float4 q = *(const float4*)&Qg[rr*HDIM + dq*4];
        float qq[4] = {q.x*ATT_SCALE, q.y*ATT_SCALE, q.z*ATT_SCALE, q.w*ATT_SCALE};
        #pragma unroll
        for (int c = 0; c < 4; c++) {
            int cc = (c + dq) & 3;
            sQ[(dq*4 + cc)*KSTR + rr] = __float_as_uint(qq[cc]);
        }
    }

    #pragma unroll
    for (int it = 0; it < 4; it++) {
        int lin = tid + 256*it;
        int rr = lin >> 4, dq = lin & 15;
        float kk4[4] = {kreg[it].x, kreg[it].y, kreg[it].z, kreg[it].w};
        #pragma unroll
        for (int c = 0; c < 4; c++) {
            int cc = (c + dq) & 3;
            sK[(dq*4 + cc)*PSTR + rr] = __float_as_uint(kk4[cc]);
        }
        *(uint4*)&sV[rr*PSTR + dq*4] = make_uint4(
            __float_as_uint(vreg[it].x), __float_as_uint(vreg[it].y),
            __float_as_uint(vreg[it].z), __float_as_uint(vreg[it].w));
    }
    __syncthreads();

    unsigned qa[8][4];
    #pragma unroll
    for (int kt = 0; kt < 8; kt++) {
        const int base = (8*kt + s)*KSTR + 16*w + g;
        qa[kt][0] = sQ[base];
        qa[kt][1] = sQ[base + 8];
        qa[kt][2] = sQ[base + 4*KSTR];
        qa[kt][3] = sQ[base + 4*KSTR + 8];
    }

    float o[8][4];
    #pragma unroll
    for (int j = 0; j < 8; j++)
        #pragma unroll
        for (int c = 0; c < 4; c++) o[j][c] = 0.f;
    float mr0 = -1e30f, mr1 = -1e30f, lr0 = 0.f, lr1 = 0.f;

    int buf = 0;
    for (int t = 0; t < SEQ/64; t++) {
        const bool more = (t + 1) < SEQ/64;
        if (more) {
            #pragma unroll
            for (int it = 0; it < 4; it++) {
                int lin = tid + 256*it;
                int rr = lin >> 4, dq = lin & 15;
                kreg[it] = *(const float4*)&Kg[(size_t)((t+1)*64 + rr)*HDIM + dq*4];
                vreg[it] = *(const float4*)&Vg[(size_t)((t+1)*64 + rr)*HDIM + dq*4];
            }
        }

        const unsigned* sKb = sK + buf*KVW;
        const unsigned* sVb = sV + buf*KVW;

        float sc[8][4];
        #pragma unroll
        for (int j = 0; j < 8; j++)
            #pragma unroll
            for (int c = 0; c < 4; c++) sc[j][c] = 0.f;
        #pragma unroll
        for (int kt = 0; kt < 8; kt++) {
            unsigned kb[8][2];
            #pragma unroll
            for (int j = 0; j < 8; j++) {
                const int base = (8*kt + s)*PSTR + 8*j + g;
                kb[j][0] = sKb[base];
                kb[j][1] = sKb[base + 4*PSTR];
            }
            #pragma unroll
            for (int j = 0; j < 8; j++)
                mma8(sc[j], qa[kt], kb[j]);
        }

        float mx0 = -1e30f, mx1 = -1e30f;
        #pragma unroll
        for (int j = 0; j < 8; j++) {
            mx0 = fmaxf(mx0, fmaxf(sc[j][0], sc[j][1]));
            mx1 = fmaxf(mx1, fmaxf(sc[j][2], sc[j][3]));
        }
        mx0 = fmaxf(mx0, __shfl_xor_sync(0xffffffffu, mx0, 1));
        mx0 = fmaxf(mx0, __shfl_xor_sync(0xffffffffu, mx0, 2));
        mx1 = fmaxf(mx1, __shfl_xor_sync(0xffffffffu, mx1, 1));
        mx1 = fmaxf(mx1, __shfl_xor_sync(0xffffffffu, mx1, 2));
        const float mn0 = fmaxf(mr0, mx0);
        const float mn1 = fmaxf(mr1, mx1);
        const float al0 = __expf(mr0 - mn0);
        const float al1 = __expf(mr1 - mn1);
        mr0 = mn0; mr1 = mn1;
        float sum0 = 0.f, sum1 = 0.f;
        #pragma unroll
        for (int j = 0; j < 8; j++) {
            sc[j][0] = __expf(sc[j][0] - mn0);
            sc[j][1] = __expf(sc[j][1] - mn0);
            sc[j][2] = __expf(sc[j][2] - mn1);
            sc[j][3] = __expf(sc[j][3] - mn1);
            sum0 += sc[j][0] + sc[j][1];
            sum1 += sc[j][2] + sc[j][3];
        }
        sum0 += __shfl_xor_sync(0xffffffffu, sum0, 1);
        sum0 += __shfl_xor_sync(0xffffffffu, sum0, 2);
        sum1 += __shfl_xor_sync(0xffffffffu, sum1, 1);
        sum1 += __shfl_xor_sync(0xffffffffu, sum1, 2);
        lr0 = lr0*al0 + sum0;
        lr1 = lr1*al1 + sum1;
        #pragma unroll
        for (int j = 0; j < 8; j++) {
            o[j][0] *= al0; o[j][1] *= al0;
            o[j][2] *= al1; o[j][3] *= al1;
        }

        __syncthreads();

        #pragma unroll
        for (int j = 0; j < 8; j++) {
            *(uint2*)&sP[r0*PSTR + 8*j + 2*s] = make_uint2(f2tf(sc[j][0]), f2tf(sc[j][1]));
            *(uint2*)&sP[r1*PSTR + 8*j + 2*s] = make_uint2(f2tf(sc[j][2]), f2tf(sc[j][3]));
        }
        if (more) {
            unsigned* sKn = sK + (buf^1)*KVW;
            unsigned* sVn = sV + (buf^1)*KVW;
            #pragma unroll
            for (int it = 0; it < 4; it++) {
                int lin = tid + 256*it;
                int rr = lin >> 4, dq = lin & 15;
                float kk4[4] = {kreg[it].x, kreg[it].y, kreg[it].z, kreg[it].w};
                #pragma unroll
                for (int c = 0; c < 4; c++) {
                    int cc = (c + dq) & 3;
                    sKn[(dq*4 + cc)*PSTR + rr] = __float_as_uint(kk4[cc]);
                }
                *(uint4*)&sVn[rr*PSTR + dq*4] = make_uint4(
                    __float_as_uint(vreg[it].x), __float_as_uint(vreg[it].y),
                    __float_as_uint(vreg[it].z), __float_as_uint(vreg[it].w));
            }
        }
        __syncthreads();

        #pragma unroll
        for (int kt = 0; kt < 8; kt++) {
            unsigned pa[4];
            pa[0] = sP[r0*PSTR + 8*kt + s];
            pa[1] = sP[r1*PSTR + 8*kt + s];
            pa[2] = sP[r0*PSTR + 8*kt + s + 4];
            pa[3] = sP[r1*PSTR + 8*kt + s + 4];
            #pragma unroll
            for (int j = 0; j < 8; j++) {
                unsigned vb[2];
                const int base = (8*kt + s)*PSTR + 8*j + g;
                vb[0] = sVb[base];
                vb[1] = sVb[base + 4*PSTR];
                mma8(o[j], pa, vb);
            }
        }
        buf ^= 1;
    }

    const float il0 = 1.f / lr0;
    const float il1 = 1.f / lr1;
    #pragma unroll
    for (int j = 0; j < 8; j++) {
        *(float2*)&Og[r0*HDIM + 8*j + 2*s] =
            make_float2(tf32r(o[j][0]*il0), tf32r(o[j][1]*il0));
        *(float2*)&Og[r1*HDIM + 8*j + 2*s] =
            make_float2(tf32r(o[j][2]*il1), tf32r(o[j][3]*il1));
    }
}

// ---------------------------------------------------------------------------
extern "C" void kernel_launch(void* const* d_in, const int* in_sizes, int n_in,
                              void* d_out, int out_size)
{
    const float* x  = (const float*)d_in[0];
    const float* Wq = (const float*)d_in[1];
    const float* bq = (const float*)d_in[2];
    const float* Wk = (const float*)d_in[3];
    const float* bk = (const float*)d_in[4];
    const float* Wv = (const float*)d_in[5];
    const float* bv = (const float*)d_in[6];
    const float* Wo = (const float*)d_in[7];
    const float* bo = (const float*)d_in[8];
    float* out = (float*)d_out;

    // pre-convert all operands to tf32 (one launch)
    {
        const int n4max = MTOT*EMBED/4;
        dim3 gc((n4max + 255)/256, 5);
        conv_all<<<gc, 256>>>(x, Wq, Wk, Wv, Wo);
    }

    const int smem_gemm = 2*STGW*(int)sizeof(unsigned);              // 110592 B
    const int smem_attn = (9216 + 4*KVW)*(int)sizeof(unsigned);      // 110592 B

    cudaFuncSetAttribute(qkv_gemm_tc, cudaFuncAttributeMaxDynamicSharedMemorySize, smem_gemm);
    cudaFuncSetAttribute(out_gemm_tc, cudaFuncAttributeMaxDynamicSharedMemorySize, smem_gemm);
    cudaFuncSetAttribute(attn_tc,     cudaFuncAttributeMaxDynamicSharedMemorySize, smem_attn);

    // QKV projections (512 threads, 16 warps)
    dim3 g1(EMBED/128, MTOT/256, 3);
    qkv_gemm_tc<<<g1, 512, smem_gemm>>>(bq, bk, bv);

    // Flash attention (unchanged)
    dim3 g2(SEQ/128, BHEADS);
    attn_tc<<<g2, 256, smem_attn>>>();

    // Output projection (512 threads, 16 warps)
    dim3 g3(EMBED/128, MTOT/256);
    out_gemm_tc<<<g3, 512, smem_gemm>>>(bo, out);
}

// round 14
// speedup vs baseline: 1.7768x; 1.7768x over previous
#include <cuda_runtime.h>
#include <cuda_fp16.h>
#include <math.h>
#include <cstdint>

#define EMBED   768
#define NHEADS  12
#define HDIM    64
#define BATCH   16
#define SEQ     1024
#define MTOT    (BATCH*SEQ)      // 16384
#define BHEADS  (BATCH*NHEADS)   // 192

// Scratch (allocation-free rule: __device__ globals) — all fp16 now
__device__ __align__(16) __half g_Qh[BHEADS*SEQ*HDIM];   // pre-scaled by 0.125
__device__ __align__(16) __half g_Kh[BHEADS*SEQ*HDIM];
__device__ __align__(16) __half g_Vh[BHEADS*SEQ*HDIM];
__device__ __align__(16) __half g_Ah[BHEADS*SEQ*HDIM];   // attention output

__device__ __align__(16) __half g_xh [MTOT*EMBED];
__device__ __align__(16) __half g_Wqh[EMBED*EMBED];
__device__ __align__(16) __half g_Wkh[EMBED*EMBED];
__device__ __align__(16) __half g_Wvh[EMBED*EMBED];
__device__ __align__(16) __half g_Woh[EMBED*EMBED];

// ---------------------------------------------------------------------------
// helpers
// ---------------------------------------------------------------------------
__device__ __forceinline__ unsigned pack2(float a, float b) {
    __half2 h = __floats2half2_rn(a, b);
    return *reinterpret_cast<unsigned*>(&h);
}

// D += A*B  (m16n8k16 fp16 in, fp32 accum, row.col)
__device__ __forceinline__ void mma16(float* d, const unsigned* a, const unsigned* b) {
    asm volatile(
        "mma.sync.aligned.m16n8k16.row.col.f32.f16.f16.f32 "
        "{%0,%1,%2,%3}, {%4,%5,%6,%7}, {%8,%9}, {%0,%1,%2,%3};"
        : "+f"(d[0]), "+f"(d[1]), "+f"(d[2]), "+f"(d[3])
        : "r"(a[0]), "r"(a[1]), "r"(a[2]), "r"(a[3]), "r"(b[0]), "r"(b[1]));
}

__device__ __forceinline__ void cpa16(unsigned saddr, const void* g) {
    asm volatile("cp.async.cg.shared.global [%0], [%1], 16;" :: "r"(saddr), "l"(g));
}
__device__ __forceinline__ void cpa_commit() {
    asm volatile("cp.async.commit_group;" ::: "memory");
}

// ---------------------------------------------------------------------------
// Pre-conversion: fp32 -> fp16 (all 5 operands, one launch)
// ---------------------------------------------------------------------------
__global__ void conv_all(const float* __restrict__ x,  const float* __restrict__ wq,
                         const float* __restrict__ wk, const float* __restrict__ wv,
                         const float* __restrict__ wo) {
    const int z = blockIdx.y;
    const float* src = (z==0) ? x : (z==1) ? wq : (z==2) ? wk : (z==3) ? wv : wo;
    __half*      dst = (z==0) ? g_xh : (z==1) ? g_Wqh : (z==2) ? g_Wkh : (z==3) ? g_Wvh : g_Woh;
    const int n4 = (z==0) ? MTOT*EMBED/4 : EMBED*EMBED/4;
    int i = blockIdx.x*blockDim.x + threadIdx.x;
    if (i < n4) {
        float4 v = ((const float4*)src)[i];
        uint2 o;
        o.x = pack2(v.x, v.y);
        o.y = pack2(v.z, v.w);
        ((uint2*)dst)[i] = o;
    }
}

// ---------------------------------------------------------------------------
// FP16 GEMM: C[m][c] = sum_k A[m][k]*W[c][k] + bias.
// 256 threads, CTA 128x128, warp tile 64x32, ktile 32 halfs, 2-stage cp.async.
// smem rows: 20 words (32 data halfs + 8 pad halfs) -> conflict-free frags.
// ---------------------------------------------------------------------------
#define KPW   20
#define GOPW  (128*KPW)          // words per operand per stage (2560)
#define GSTW  (2*GOPW)           // words per stage (5120)

// fill 128 rows x 32 halfs: 4 chunks of 16B per row, 512 chunks, 2/thread
__device__ __forceinline__ void fillh(unsigned dstb, const __half* __restrict__ src,
                                      int row0, int k0h, int tid) {
    #pragma unroll
    for (int it = 0; it < 2; it++) {
        int lin = tid + 256*it;
        int rr = lin >> 2, ch = lin & 3;
        cpa16(dstb + rr*80 + ch*16, src + (size_t)(row0+rr)*EMBED + k0h + ch*8);
    }
}
// fill gathering from g_Ah [b][h][n][d]
__device__ __forceinline__ void fillh_gather(unsigned dstb, int m0, int k0h, int tid) {
    #pragma unroll
    for (int it = 0; it < 2; it++) {
        int lin = tid + 256*it;
        int rr = lin >> 2, ch = lin & 3;
        const int m  = m0 + rr;
        const int b_ = m >> 10;
        const int nn = m & 1023;
        const int k  = k0h + ch*8;
        const int h  = k >> 6;
        const int d  = k & 63;
        cpa16(dstb + rr*80 + ch*16, g_Ah + (((size_t)b_*NHEADS + h)*SEQ + nn)*HDIM + d);
    }
}

__device__ __forceinline__ void compute_fp16(const unsigned* __restrict__ As,
                                             const unsigned* __restrict__ Bs,
                                             float acc[4][4][4],
                                             int wm, int wn, int g, int s) {
    #pragma unroll
    for (int kt = 0; kt < 2; kt++) {
        const int kc = kt*8 + s;
        unsigned a[4][4], b[4][2];
        #pragma unroll
        for (int i = 0; i < 4; i++) {
            const unsigned* p = &As[(wm + 16*i + g)*KPW + kc];
            a[i][0] = p[0];
            a[i][1] = p[8*KPW];
            a[i][2] = p[4];
            a[i][3] = p[8*KPW + 4];
        }
        #pragma unroll
        for (int j = 0; j < 4; j++) {
            const unsigned* p = &Bs[(wn + 8*j + g)*KPW + kc];
            b[j][0] = p[0];
            b[j][1] = p[4];
        }
        #pragma unroll
        for (int i = 0; i < 4; i++)
            #pragma unroll
            for (int j = 0; j < 4; j++)
                mma16(acc[i][j], a[i], b[j]);
    }
}

#define NKT (EMBED/32)   // 24

__global__ __launch_bounds__(256) void qkv_gemm_h(
    const float* __restrict__ bq, const float* __restrict__ bk, const float* __restrict__ bv)
{
    const int p = blockIdx.z;
    const __half* __restrict__ Wt   = (p==0) ? g_Wqh : (p==1 ? g_Wkh : g_Wvh);
    const float*  __restrict__ bias = (p==0) ? bq : (p==1 ? bk : bv);
    __half*       __restrict__ outp = (p==0) ? g_Qh : (p==1 ? g_Kh : g_Vh);
    const float scp = (p==0) ? 0.125f : 1.0f;   // fold attention scale into Q

    extern __shared__ unsigned smg[];
    const unsigned sbase = (unsigned)__cvta_generic_to_shared(smg);

    const int tid  = threadIdx.x;
    const int w    = tid >> 5;
    const int lane = tid & 31;
    const int g    = lane >> 2;
    const int s    = lane & 3;
    const int wm   = (w & 1) * 64;
    const int wn   = (w >> 1) * 32;
    const int m0   = blockIdx.y * 128;
    const int n0   = blockIdx.x * 128;

    float acc[4][4][4];
    #pragma unroll
    for (int i = 0; i < 4; i++)
        #pragma unroll
        for (int j = 0; j < 4; j++)
            #pragma unroll
            for (int c = 0; c < 4; c++) acc[i][j][c] = 0.f;

    fillh(sbase,           g_xh, m0, 0, tid);
    fillh(sbase + GOPW*4,  Wt,   n0, 0, tid);
    cpa_commit();

    int buf = 0;
    for (int i = 0; i < NKT; i++) {
        const bool more = (i + 1) < NKT;
        if (more) {
            unsigned st = sbase + (buf^1)*GSTW*4;
            fillh(st,          g_xh, m0, (i+1)*32, tid);
            fillh(st + GOPW*4, Wt,   n0, (i+1)*32, tid);
            cpa_commit();
            asm volatile("cp.async.wait_group 1;" ::: "memory");
        } else {
            asm volatile("cp.async.wait_group 0;" ::: "memory");
        }
        __syncthreads();
        const unsigned* st = smg + buf*GSTW;
        compute_fp16(st, st + GOPW, acc, wm, wn, g, s);
        __syncthreads();
        buf ^= 1;
    }

    // Epilogue: (+bias)*scp, round to half, scatter to [b][h][n][d]
    #pragma unroll
    for (int i = 0; i < 4; i++) {
        const int m  = m0 + wm + 16*i + g;
        const int b_ = m >> 10;
        const int nn = m & 1023;
        #pragma unroll
        for (int j = 0; j < 4; j++) {
            const int c  = n0 + wn + 8*j + 2*s;
            const int h  = c >> 6;
            const int d  = c & 63;
            const float b0v = bias[c], b1v = bias[c+1];
            unsigned v0 = pack2((acc[i][j][0] + b0v)*scp, (acc[i][j][1] + b1v)*scp);
            unsigned v1 = pack2((acc[i][j][2] + b0v)*scp, (acc[i][j][3] + b1v)*scp);
            *(unsigned*)&outp[(((size_t)b_*NHEADS + h)*SEQ + nn    )*HDIM + d] = v0;
            *(unsigned*)&outp[(((size_t)b_*NHEADS + h)*SEQ + nn + 8)*HDIM + d] = v1;
        }
    }
}

__global__ __launch_bounds__(256) void out_gemm_h(
    const float* __restrict__ bo, float* __restrict__ out)
{
    extern __shared__ unsigned smg[];
    const unsigned sbase = (unsigned)__cvta_generic_to_shared(smg);

    const int tid  = threadIdx.x;
    const int w    = tid >> 5;
    const int lane = tid & 31;
    const int g    = lane >> 2;
    const int s    = lane & 3;
    const int wm   = (w & 1) * 64;
    const int wn   = (w >> 1) * 32;
    const int m0   = blockIdx.y * 128;
    const int n0   = blockIdx.x * 128;

    float acc[4][4][4];
    #pragma unroll
    for (int i = 0; i < 4; i++)
        #pragma unroll
        for (int j = 0; j < 4; j++)
            #pragma unroll
            for (int c = 0; c < 4; c++) acc[i][j][c] = 0.f;

    fillh_gather(sbase, m0, 0, tid);
    fillh(sbase + GOPW*4, g_Woh, n0, 0, tid);
    cpa_commit();

    int buf = 0;
    for (int i = 0; i < NKT; i++) {
        const bool more = (i + 1) < NKT;
        if (more) {
            unsigned st = sbase + (buf^1)*GSTW*4;
            fillh_gather(st, m0, (i+1)*32, tid);
            fillh(st + GOPW*4, g_Woh, n0, (i+1)*32, tid);
            cpa_commit();
            asm volatile("cp.async.wait_group 1;" ::: "memory");
        } else {
            asm volatile("cp.async.wait_group 0;" ::: "memory");
        }
        __syncthreads();
        const unsigned* st = smg + buf*GSTW;
        compute_fp16(st, st + GOPW, acc, wm, wn, g, s);
        __syncthreads();
        buf ^= 1;
    }

    // Epilogue: fp32 out + bias
    #pragma unroll
    for (int i = 0; i < 4; i++) {
        const int m = m0 + wm + 16*i + g;
        #pragma unroll
        for (int j = 0; j < 4; j++) {
            const int c = n0 + wn + 8*j + 2*s;
            const float b0v = bo[c], b1v = bo[c+1];
            float2 v0 = make_float2(acc[i][j][0] + b0v, acc[i][j][1] + b1v);
            float2 v1 = make_float2(acc[i][j][2] + b0v, acc[i][j][3] + b1v);
            *(float2*)&out[(size_t)m*EMBED + c]     = v0;
            *(float2*)&out[(size_t)(m+8)*EMBED + c] = v1;
        }
    }
}

// ---------------------------------------------------------------------------
// FP16 flash attention.  Br=128, Bc=64, 256 threads / 8 warps.
// sQ [q=128][36w] (aliased by sP after qa cached) | sK[2][key=64][36w] |
// sV[2][d=64][37w] (transposed).  Q pre-scaled in qkv epilogue.
// ---------------------------------------------------------------------------
#define AQW   36                 // words per sQ/sP/sK row
#define AVW   37                 // words per sV row
#define SQ_OFF  0
#define SK_OFF  4608             // 128*36
#define SKBUF   2304             // 64*36
#define SV_OFF  (SK_OFF + 2*SKBUF)   // 9216
#define SVBUF   2368             // 64*37
#define ATTW    (SV_OFF + 2*SVBUF)   // 13952 words = 55808 B

__global__ __launch_bounds__(256) void attn_h()
{
    extern __shared__ unsigned smu[];
    const unsigned sbase = (unsigned)__cvta_generic_to_shared(smu);
    unsigned* sQ = smu;                 // also sP
    __half*  smh = reinterpret_cast<__half*>(smu);

    const int tid  = threadIdx.x;
    const int w    = tid >> 5;
    const int lane = tid & 31;
    const int g    = lane >> 2;
    const int s    = lane & 3;
    const int bh   = blockIdx.y;
    const int q0   = blockIdx.x * 128;
    const int r0   = 16*w + g;
    const int r1   = r0 + 8;

    const __half* __restrict__ Qg = g_Qh + ((size_t)bh*SEQ + q0)*HDIM;
    const __half* __restrict__ Kg = g_Kh + (size_t)bh*SEQ*HDIM;
    const __half* __restrict__ Vg = g_Vh + (size_t)bh*SEQ*HDIM;
    __half* __restrict__ Og = g_Ah + ((size_t)bh*SEQ + q0)*HDIM;

    // ---- prologue: cp.async Q (128 rows) + K tile 0 (64 rows) ----
    #pragma unroll
    for (int it = 0; it < 4; it++) {
        int lin = tid + 256*it;
        int rr = lin >> 3, ch = lin & 7;          // 128 rows x 8 chunks
        cpa16(sbase + rr*144 + ch*16, Qg + rr*HDIM + ch*8);
    }
    #pragma unroll
    for (int it = 0; it < 2; it++) {
        int lin = tid + 256*it;
        int rr = lin >> 3, ch = lin & 7;          // 64 rows x 8 chunks
        cpa16(sbase + SK_OFF*4 + rr*144 + ch*16, Kg + rr*HDIM + ch*8);
    }
    cpa_commit();

    // V tile 0: read half2 along d, transpose into sV[d][key]
    unsigned vreg[8];
    #pragma unroll
    for (int it = 0; it < 8; it++) {
        int lin = tid + 256*it;
        int rr = lin >> 5, c = lin & 31;          // key, d-pair
        vreg[it] = *(const unsigned*)&Vg[rr*HDIM + 2*c];
    }
    asm volatile("cp.async.wait_group 0;" ::: "memory");
    #pragma unroll
    for (int it = 0; it < 8; it++) {
        int lin = tid + 256*it;
        int rr = lin >> 5, c = lin & 31;
        __half2 hv = *reinterpret_cast<__half2*>(&vreg[it]);
        smh[(SV_OFF*2) + (2*c  )*(2*AVW) + rr] = __low2half(hv);
        smh[(SV_OFF*2) + (2*c+1)*(2*AVW) + rr] = __high2half(hv);
    }
    __syncthreads();

    // cache Q A-fragments (fp16: 16 regs)
    unsigned qa[4][4];
    #pragma unroll
    for (int kt = 0; kt < 4; kt++) {
        const unsigned* p = &sQ[r0*AQW + 8*kt + s];
        qa[kt][0] = p[0];
        qa[kt][1] = p[8*AQW];
        qa[kt][2] = p[4];
        qa[kt][3] = p[8*AQW + 4];
    }

    float o[8][4];
    #pragma unroll
    for (int j = 0; j < 8; j++)
        #pragma unroll
        for (int c = 0; c < 4; c++) o[j][c] = 0.f;
    float mr0 = -1e30f, mr1 = -1e30f, lr0 = 0.f, lr1 = 0.f;

    int buf = 0;
    for (int t = 0; t < SEQ/64; t++) {
        const bool more = (t + 1) < SEQ/64;
        // prefetch: K(t+1) via cp.async into other buffer; V(t+1) into regs
        if (more) {
            const __half* Kn = Kg + (size_t)(t+1)*64*HDIM;
            unsigned kdst = sbase + (SK_OFF + (buf^1)*SKBUF)*4;
            #pragma unroll
            for (int it = 0; it < 2; it++) {
                int lin = tid + 256*it;
                int rr = lin >> 3, ch = lin & 7;
                cpa16(kdst + rr*144 + ch*16, Kn + rr*HDIM + ch*8);
            }
            cpa_commit();
            const __half* Vn = Vg + (size_t)(t+1)*64*HDIM;
            #pragma unroll
            for (int it = 0; it < 8; it++) {
                int lin = tid + 256*it;
                int rr = lin >> 5, c = lin & 31;
                vreg[it] = *(const unsigned*)&Vn[rr*HDIM + 2*c];
            }
        }

        const unsigned* sKb = smu + SK_OFF + buf*SKBUF;
        const unsigned* sVb = smu + SV_OFF + buf*SVBUF;

        // ---- S = Q @ K^T (128x64), fp16 mma, fp32 accum ----
        float sc[8][4];
        #pragma unroll
        for (int j = 0; j < 8; j++)
            #pragma unroll
            for (int c = 0; c < 4; c++) sc[j][c] = 0.f;
        #pragma unroll
        for (int kt = 0; kt < 4; kt++) {
            unsigned kb[8][2];
            #pragma unroll
            for (int j = 0; j < 8; j++) {
                const unsigned* p = &sKb[(8*j + g)*AQW + 8*kt + s];
                kb[j][0] = p[0];
                kb[j][1] = p[4];
            }
            #pragma unroll
            for (int j = 0; j < 8; j++)
                mma16(sc[j], qa[kt], kb[j]);
        }

        // ---- online softmax (fp32 registers) ----
        float mx0 = -1e30f, mx1 = -1e30f;
        #pragma unroll
        for (int j = 0; j < 8; j++) {
            mx0 = fmaxf(mx0, fmaxf(sc[j][0], sc[j][1]));
            mx1 = fmaxf(mx1, fmaxf(sc[j][2], sc[j][3]));
        }
        mx0 = fmaxf(mx0, __shfl_xor_sync(0xffffffffu, mx0, 1));
        mx0 = fmaxf(mx0, __shfl_xor_sync(0xffffffffu, mx0, 2));
        mx1 = fmaxf(mx1, __shfl_xor_sync(0xffffffffu, mx1, 1));
        mx1 = fmaxf(mx1, __shfl_xor_sync(0xffffffffu, mx1, 2));
        const float mn0 = fmaxf(mr0, mx0);
        const float mn1 = fmaxf(mr1, mx1);
        const float al0 = __expf(mr0 - mn0);
        const float al1 = __expf(mr1 - mn1);
        mr0 = mn0; mr1 = mn1;
        float sum0 = 0.f, sum1 = 0.f;
        #pragma unroll
        for (int j = 0; j < 8; j++) {
            sc[j][0] = __expf(sc[j][0] - mn0);
            sc[j][1] = __expf(sc[j][1] - mn0);
            sc[j][2] = __expf(sc[j][2] - mn1);
            sc[j][3] = __expf(sc[j][3] - mn1);
            sum0 += sc[j][0] + sc[j][1];
            sum1 += sc[j][2] + sc[j][3];
        }
        sum0 += __shfl_xor_sync(0xffffffffu, sum0, 1);
        sum0 += __shfl_xor_sync(0xffffffffu, sum0, 2);
        sum1 += __shfl_xor_sync(0xffffffffu, sum1, 1);
        sum1 += __shfl_xor_sync(0xffffffffu, sum1, 2);
        lr0 = lr0*al0 + sum0;
        lr1 = lr1*al1 + sum1;
        #pragma unroll
        for (int j = 0; j < 8; j++) {
            o[j][0] *= al0; o[j][1] *= al0;
            o[j][2] *= al1; o[j][3] *= al1;
        }

        if (more) asm volatile("cp.async.wait_group 0;" ::: "memory");
        __syncthreads();   // prev PV readers of sP and V(buf^1) done

        // ---- store P (half2) + transpose-store V(t+1) ----
        #pragma unroll
        for (int j = 0; j < 8; j++) {
            sQ[r0*AQW + 4*j + s] = pack2(sc[j][0], sc[j][1]);
            sQ[r1*AQW + 4*j + s] = pack2(sc[j][2], sc[j][3]);
        }
        if (more) {
            const int vb_off = (SV_OFF + (buf^1)*SVBUF)*2;
            #pragma unroll
            for (int it = 0; it < 8; it++) {
                int lin = tid + 256*it;
                int rr = lin >> 5, c = lin & 31;
                __half2 hv = *reinterpret_cast<__half2*>(&vreg[it]);
                smh[vb_off + (2*c  )*(2*AVW) + rr] = __low2half(hv);
                smh[vb_off + (2*c+1)*(2*AVW) + rr] = __high2half(hv);
            }
        }
        __syncthreads();

        // ---- O += P @ V ----
        #pragma unroll
        for (int kt = 0; kt < 4; kt++) {
            unsigned pa[4];
            pa[0] = sQ[r0*AQW + 8*kt + s];
            pa[1] = sQ[r1*AQW + 8*kt + s];
            pa[2] = sQ[r0*AQW + 8*kt + s + 4];
            pa[3] = sQ[r1*AQW + 8*kt + s + 4];
            #pragma unroll
            for (int j = 0; j < 8; j++) {
                unsigned vb[2];
                const unsigned* p = &sVb[(8*j + g)*AVW + 8*kt + s];
                vb[0] = p[0];
                vb[1] = p[4];
                mma16(o[j], pa, vb);
            }
        }
        buf ^= 1;
    }

    // ---- normalize + store as half ----
    const float il0 = 1.f / lr0;
    const float il1 = 1.f / lr1;
    #pragma unroll
    for (int j = 0; j < 8; j++) {
        *(unsigned*)&Og[r0*HDIM + 8*j + 2*s] = pack2(o[j][0]*il0, o[j][1]*il0);
        *(unsigned*)&Og[r1*HDIM + 8*j + 2*s] = pack2(o[j][2]*il1, o[j][3]*il1);
    }
}

// ---------------------------------------------------------------------------
extern "C" void kernel_launch(void* const* d_in, const int* in_sizes, int n_in,
                              void* d_out, int out_size)
{
    const float* x  = (const float*)d_in[0];
    const float* Wq = (const float*)d_in[1];
    const float* bq = (const float*)d_in[2];
    const float* Wk = (const float*)d_in[3];
    const float* bk = (const float*)d_in[4];
    const float* Wv = (const float*)d_in[5];
    const float* bv = (const float*)d_in[6];
    const float* Wo = (const float*)d_in[7];
    const float* bo = (const float*)d_in[8];
    float* out = (float*)d_out;

    // pre-convert all operands to fp16 (one launch)
    {
        const int n4max = MTOT*EMBED/4;
        dim3 gc((n4max + 255)/256, 5);
        conv_all<<<gc, 256>>>(x, Wq, Wk, Wv, Wo);
    }

    const int smem_gemm = 2*GSTW*(int)sizeof(unsigned);   // 40960 B
    const int smem_attn = ATTW*(int)sizeof(unsigned);     // 55808 B

    cudaFuncSetAttribute(qkv_gemm_h, cudaFuncAttributeMaxDynamicSharedMemorySize, smem_gemm);
    cudaFuncSetAttribute(out_gemm_h, cudaFuncAttributeMaxDynamicSharedMemorySize, smem_gemm);
    cudaFuncSetAttribute(attn_h,     cudaFuncAttributeMaxDynamicSharedMemorySize, smem_attn);

    // QKV projections (fp16 tensor cores)
    dim3 g1(EMBED/128, MTOT/128, 3);
    qkv_gemm_h<<<g1, 256, smem_gemm>>>(bq, bk, bv);

    // Flash attention (fp16 tensor cores)
    dim3 g2(SEQ/128, BHEADS);
    attn_h<<<g2, 256, smem_attn>>>();

    // Output projection
    dim3 g3(EMBED/128, MTOT/128);
    out_gemm_h<<<g3, 256, smem_gemm>>>(bo, out);
}